// round 5
// baseline (speedup 1.0000x reference)
#include <cuda_runtime.h>
#include <math.h>

// Problem constants
#define NB   256
#define NL   256
#define NC   32
#define NS   32
#define NROWS (NB*NL)
#define C_LOG2PI 58.812066125099048f   // 32 * log(2*pi)
#define LROW 544   // padded triangular per state: row i starts at tri(i)+ceil(i/2), pads=0

#define FULLMASK 0xffffffffu
typedef unsigned long long ull;

// ---------------- packed f32x2 helpers ----------------
__device__ __forceinline__ ull pack2(float a, float b) {
    ull r; asm("mov.b64 %0, {%1, %2};" : "=l"(r) : "f"(a), "f"(b)); return r;
}
__device__ __forceinline__ float2 unpack2(ull v) {
    float2 r; asm("mov.b64 {%0, %1}, %2;" : "=f"(r.x), "=f"(r.y) : "l"(v)); return r;
}
__device__ __forceinline__ ull fma2(ull a, ull b, ull c) {
    ull d; asm("fma.rn.f32x2 %0, %1, %2, %3;" : "=l"(d) : "l"(a), "l"(b), "l"(c)); return d;
}
__device__ __forceinline__ ulonglong2 lds128(unsigned addr) {
    ulonglong2 v;
    asm("ld.shared.v2.u64 {%0, %1}, [%2];" : "=l"(v.x), "=l"(v.y) : "r"(addr));
    return v;
}
__device__ __forceinline__ ull lds64(unsigned addr) {
    ull v; asm("ld.shared.b64 %0, [%1];" : "=l"(v) : "r"(addr)); return v;
}

// ---------------- device scratch ----------------
__device__ ull   g_Linv2[NS * LROW];     // padded-tri T^-1, duplicated f32x2 (pads = 0)
__device__ ull   g_ncvec2[NS * 32];      // -(Linv*mu), duplicated
__device__ float g_ld[NS];               // logdet = 2*sum(cc_ii)
__device__ float g_log_trans[NS * NS];
__device__ float g_log_init[NS];
__device__ int   g_rowargmax[NS];
__device__ float g_emlp[NROWS * NS];     // [row][state]

// =====================================================================
// Kernel 0: prep. Grid 32, block 64 (2 warps).
// Warp 0 of block s: Linv_s (forward substitution, rcp-diag), logdet,
//                    ncvec_s = -Linv_s*mu_s, padded-tri store.
// Warp 1 of block s: transition row s softmax/log/argmax; block 0 also init.
// =====================================================================
__global__ void __launch_bounds__(64) prep_kernel(const float* __restrict__ cc,
                                                  const float* __restrict__ means,
                                                  const float* __restrict__ tm,
                                                  const float* __restrict__ idist) {
    const int s    = blockIdx.x;
    const int warp = threadIdx.x >> 5;
    const int lane = threadIdx.x & 31;

    if (warp == 0) {
        __shared__ float T[32][33];
        __shared__ float LI[32][33];
        __shared__ float Mu[32];
        __shared__ float Rd[32];

        // T = tril(cc[s]) with exp on diagonal
        #pragma unroll
        for (int i = 0; i < 32; i++) {
            float v = cc[s * 1024 + i * 32 + lane];
            if (lane > i) v = 0.0f;
            else if (lane == i) v = expf(v);
            T[i][lane] = v;
        }
        Mu[lane] = means[s * 32 + lane];

        // logdet = 2 * sum(cc_ii)
        float dsum = cc[s * 1024 + lane * 33];
        #pragma unroll
        for (int o = 16; o; o >>= 1) dsum += __shfl_xor_sync(FULLMASK, dsum, o);
        if (lane == 0) g_ld[s] = 2.0f * dsum;
        __syncwarp();

        Rd[lane] = __frcp_rn(T[lane][lane]);
        __syncwarp();

        // Forward substitution: lane owns column `lane` of T^-1.
        float x[32];
        #pragma unroll
        for (int i = 0; i < 32; i++) {
            float se = (lane == i) ? 1.0f : 0.0f;
            float so = 0.0f;
            #pragma unroll
            for (int k = 0; k < i; k += 2) se -= T[i][k] * x[k];
            #pragma unroll
            for (int k = 1; k < i; k += 2) so -= T[i][k] * x[k];
            x[i] = (lane <= i) ? ((se + so) * Rd[i]) : 0.0f;
            LI[i][lane] = x[i];
        }
        __syncwarp();

        // ncvec[i] = -sum_k Linv[i][k] * mu[k]   (lane = i)
        float ncv = 0.0f;
        #pragma unroll
        for (int k = 0; k < 32; k++) ncv -= LI[lane][k] * Mu[k];
        g_ncvec2[s * 32 + lane] = pack2(ncv, ncv);

        // padded-triangular duplicated Linv store
        #pragma unroll
        for (int i = 0; i < 32; i++) {
            const int Ri = i * (i + 1) / 2 + ((i + 1) >> 1);
            if (lane <= i)
                g_Linv2[s * LROW + Ri + lane] = pack2(x[i], x[i]);
            if (((i & 1) == 0) && lane == i + 1)
                g_Linv2[s * LROW + Ri + i + 1] = 0ull;
        }
    } else {
        // transition row s
        float tv = tm[s * 32 + lane];
        float m2 = tv;
        #pragma unroll
        for (int o = 16; o; o >>= 1) m2 = fmaxf(m2, __shfl_xor_sync(FULLMASK, m2, o));
        float ee = expf(tv - m2);
        float ssum = ee;
        #pragma unroll
        for (int o = 16; o; o >>= 1) ssum += __shfl_xor_sync(FULLMASK, ssum, o);
        g_log_trans[s * 32 + lane] = logf(ee / ssum + 1e-8f);

        float bv = tv; int bi = lane;
        #pragma unroll
        for (int o = 16; o; o >>= 1) {
            float ov = __shfl_xor_sync(FULLMASK, bv, o);
            int   oi = __shfl_xor_sync(FULLMASK, bi, o);
            if (ov > bv || (ov == bv && oi < bi)) { bv = ov; bi = oi; }
        }
        if (lane == 0) g_rowargmax[s] = bi;

        if (s == 0) {
            float v = idist[lane];
            float mx = v;
            #pragma unroll
            for (int o = 16; o; o >>= 1) mx = fmaxf(mx, __shfl_xor_sync(FULLMASK, mx, o));
            float e = expf(v - mx);
            float sm = e;
            #pragma unroll
            for (int o = 16; o; o >>= 1) sm += __shfl_xor_sync(FULLMASK, sm, o);
            g_log_init[lane] = (v - mx) - logf(sm);
        }
    }
}

// =====================================================================
// Kernel 1: emission log probs — register-tiled.
// Block = 128 thr (pg = lane 0..31, sg = warp 0..3).
// Tile: 256 rows (128 f32x2 pairs, channel-major in smem) x 16 states (by half).
// Thread: 4 pairs (pg+32q) x 4 states (sg*4+s4): 16 f32x2 accumulators.
// Per (i, jpair): 8 x LDS.64 + 4 L LDS.128 -> 32 FFMA2.
// smem: L 16*544 + X 32*128 + ncvec 16*32 ull + 16 f = ~104KB -> 2 blocks/SM.
// =====================================================================
__global__ void __launch_bounds__(128) emlp_kernel(const float* __restrict__ em) {
    extern __shared__ ull sh[];
    // sL: [0, 8704)   sX: [8704, 12800)   sC: [12800, 13312)   sLd: 16 floats after
    const int by  = blockIdx.y;            // state half
    const int tid = threadIdx.x;
    const int pg  = tid & 31;
    const int sg  = tid >> 5;

    const ull* gL = g_Linv2 + by * 16 * LROW;
    for (int i = tid; i < 16 * LROW; i += 128) sh[i] = gL[i];
    const ull* gC = g_ncvec2 + by * 512;
    for (int i = tid; i < 512; i += 128) sh[12800 + i] = gC[i];
    float* sLd = (float*)(sh + 13312);
    if (tid < 16) sLd[tid] = g_ld[by * 16 + tid];

    // stage X: thread t owns pair t = rows (row0+2t, row0+2t+1), channel-major
    const int row0 = blockIdx.x * 256;
    {
        const float4* pa = (const float4*)(em + (size_t)(row0 + 2 * tid) * 32);
        #pragma unroll
        for (int q = 0; q < 8; q++) {
            float4 a = pa[q];          // row 2t, channels 4q..4q+3
            float4 b = pa[8 + q];      // row 2t+1
            sh[8704 + (4*q+0) * 128 + tid] = pack2(a.x, b.x);
            sh[8704 + (4*q+1) * 128 + tid] = pack2(a.y, b.y);
            sh[8704 + (4*q+2) * 128 + tid] = pack2(a.z, b.z);
            sh[8704 + (4*q+3) * 128 + tid] = pack2(a.w, b.w);
        }
    }
    __syncthreads();

    const unsigned base = (unsigned)__cvta_generic_to_shared(sh);
    const unsigned Xb   = base + 8704u * 8u;
    const unsigned Cb   = base + 12800u * 8u;
    unsigned Lsb[4], xo[4];
    #pragma unroll
    for (int s4 = 0; s4 < 4; s4++) Lsb[s4] = base + (unsigned)((sg * 4 + s4) * LROW * 8);
    #pragma unroll
    for (int q = 0; q < 4; q++)    xo[q]  = Xb + (unsigned)((pg + 32 * q) * 8);

    ull ma[4][4];
    #pragma unroll
    for (int p4 = 0; p4 < 4; p4++)
        #pragma unroll
        for (int s4 = 0; s4 < 4; s4++) ma[p4][s4] = 0ull;

    for (int i = 0; i < 32; i++) {
        // init solved accumulators with -Linv*mu
        ull sv[4][4];
        #pragma unroll
        for (int s4 = 0; s4 < 4; s4++) {
            ull cv = lds64(Cb + (unsigned)(((sg * 4 + s4) * 32 + i) * 8));
            #pragma unroll
            for (int p4 = 0; p4 < 4; p4++) sv[p4][s4] = cv;
        }
        const int RB = i * (i + 1) / 2 + ((i + 1) >> 1);
        const int npairs = (i + 2) >> 1;
        const unsigned lofs = (unsigned)(RB * 8);
        for (int jp = 0; jp < npairs; jp++) {
            const unsigned jb = (unsigned)(jp * 2 * 128 * 8);
            ull xv0[4], xv1[4];
            #pragma unroll
            for (int q = 0; q < 4; q++) {
                xv0[q] = lds64(xo[q] + jb);
                xv1[q] = lds64(xo[q] + jb + 1024u);
            }
            ulonglong2 Lv[4];
            #pragma unroll
            for (int s4 = 0; s4 < 4; s4++)
                Lv[s4] = lds128(Lsb[s4] + lofs + (unsigned)(jp * 16));
            #pragma unroll
            for (int p4 = 0; p4 < 4; p4++)
                #pragma unroll
                for (int s4 = 0; s4 < 4; s4++) {
                    sv[p4][s4] = fma2(Lv[s4].x, xv0[p4], sv[p4][s4]);
                    sv[p4][s4] = fma2(Lv[s4].y, xv1[p4], sv[p4][s4]);  // pads=0 safe
                }
        }
        #pragma unroll
        for (int p4 = 0; p4 < 4; p4++)
            #pragma unroll
            for (int s4 = 0; s4 < 4; s4++)
                ma[p4][s4] = fma2(sv[p4][s4], sv[p4][s4], ma[p4][s4]);
    }

    // epilogue: stage [256 rows][16 states] in smem (reuse X region), then coalesced store
    __syncthreads();
    float* so = (float*)(sh + 8704);
    #pragma unroll
    for (int p4 = 0; p4 < 4; p4++) {
        const int r = 2 * (pg + 32 * p4);
        #pragma unroll
        for (int s4 = 0; s4 < 4; s4++) {
            float2 m = unpack2(ma[p4][s4]);
            const int c  = sg * 4 + s4;
            const float k = sLd[c] + C_LOG2PI;
            so[r * 16 + c]       = -0.5f * (m.x + k);
            so[(r + 1) * 16 + c] = -0.5f * (m.y + k);
        }
    }
    __syncthreads();
    const float4* so4 = (const float4*)so;
    #pragma unroll
    for (int idx = tid; idx < 1024; idx += 128) {
        const int r = idx >> 2, c4 = idx & 3;
        *(float4*)(g_emlp + (size_t)(row0 + r) * 32 + by * 16 + c4 * 4) = so4[idx];
    }
}

// =====================================================================
// Kernel 2: fused Viterbi + AR prediction. One block (256 thr) per batch.
// =====================================================================
__global__ void __launch_bounds__(256) vp_kernel(const float* __restrict__ em,
                                                 const float* __restrict__ W,
                                                 const float* __restrict__ means,
                                                 float* __restrict__ out) {
    const int b    = blockIdx.x;
    const int lane = threadIdx.x & 31;
    const int g    = threadIdx.x >> 5;

    __shared__ float red[8][32];
    __shared__ int   s_state;

    const float* ebm = em + (size_t)b * NL * NC;
    float acc = 0.0f;
    #pragma unroll
    for (int l = 0; l < 32; l++) {
        const int ll = g * 32 + l;
        acc += ebm[ll * NC + lane] * W[ll * NC + lane];
    }
    red[g][lane] = acc;

    if (g == 0) {
        float ltcol[32];
        #pragma unroll
        for (int i = 0; i < 32; i++) ltcol[i] = g_log_trans[i * 32 + lane];

        const float* eb = g_emlp + (size_t)b * NL * NS;
        float delta = g_log_init[lane] + eb[lane];

        #pragma unroll 4
        for (int t = 1; t < NL; t++) {
            const float emv = eb[t * NS + lane];
            float v[32];
            #pragma unroll
            for (int i = 0; i < 32; i++)
                v[i] = __shfl_sync(FULLMASK, delta, i) + ltcol[i];
            #pragma unroll
            for (int st = 16; st >= 1; st >>= 1) {
                #pragma unroll
                for (int i = 0; i < 16; i++)
                    if (i < st) v[i] = fmaxf(v[i], v[i + st]);
            }
            delta = v[0] + emv;
        }

        float bv = delta; int bi = lane;
        #pragma unroll
        for (int o = 16; o; o >>= 1) {
            float ov = __shfl_xor_sync(FULLMASK, bv, o);
            int   oi = __shfl_xor_sync(FULLMASK, bi, o);
            if (ov > bv || (ov == bv && oi < bi)) { bv = ov; bi = oi; }
        }
        if (lane == 0) s_state = g_rowargmax[bi];
    }
    __syncthreads();

    if (g == 0) {
        float ssum = 0.0f;
        #pragma unroll
        for (int k = 0; k < 8; k++) ssum += red[k][lane];
        out[b * NC + lane] = ssum + means[s_state * NC + lane];
    }
}

// =====================================================================
extern "C" void kernel_launch(void* const* d_in, const int* in_sizes, int n_in,
                              void* d_out, int out_size) {
    const float* em    = (const float*)d_in[0];
    const float* tm    = (const float*)d_in[1];
    const float* idist = (const float*)d_in[2];
    const float* means = (const float*)d_in[3];
    const float* cc    = (const float*)d_in[4];
    const float* W     = (const float*)d_in[5];
    float* out = (float*)d_out;

    prep_kernel<<<NS, 64>>>(cc, means, tm, idist);

    const int shbytes = 13312 * (int)sizeof(ull) + 16 * (int)sizeof(float);
    cudaFuncSetAttribute(emlp_kernel, cudaFuncAttributeMaxDynamicSharedMemorySize, shbytes);
    emlp_kernel<<<dim3(NROWS / 256, 2), 128, shbytes>>>(em);

    vp_kernel<<<NB, 256>>>(em, W, means, out);
}